// round 2
// baseline (speedup 1.0000x reference)
#include <cuda_runtime.h>

#define FDIM 64
#define RDIM 4
#define F4   16          // float4 chunks per feature row
#define E_MAX 100000

// he_feat scratch: E x F floats = 25.6 MB, device global (no allocs allowed).
__device__ float g_he[(size_t)E_MAX * FDIM];

__device__ __forceinline__ void red_add_v4(float* addr, float a, float b, float c, float d) {
    asm volatile("red.global.add.v4.f32 [%0], {%1,%2,%3,%4};"
                 :: "l"(addr), "f"(a), "f"(b), "f"(c), "f"(d)
                 : "memory");
}

// Init: out[:, 3, :] = x ; out[:, 0:3, :] = 0 ; g_he = 0.
__global__ void init_kernel(const float* __restrict__ x, float* __restrict__ out,
                            int N, int E) {
    int tid = blockIdx.x * blockDim.x + threadIdx.x;
    int total_out = N * (RDIM * F4);   // out in float4 units
    int total_he  = E * F4;
    if (tid < total_out) {
        int n = tid / (RDIM * F4);
        int c = tid % (RDIM * F4);
        float4* out4 = reinterpret_cast<float4*>(out);
        if (c >= 3 * F4) {
            const float4* x4 = reinterpret_cast<const float4*>(x);
            out4[tid] = x4[n * F4 + (c - 3 * F4)];
        } else {
            out4[tid] = make_float4(0.f, 0.f, 0.f, 0.f);
        }
    } else {
        int k = tid - total_out;
        if (k < total_he) {
            reinterpret_cast<float4*>(g_he)[k] = make_float4(0.f, 0.f, 0.f, 0.f);
        }
    }
}

// Phase A: he_feat[col] += x[row] * val.  16 threads per nnz, one float4 each.
__global__ void scatter_he_kernel(const float* __restrict__ x,
                                  const float* __restrict__ vals,
                                  const int* __restrict__ rows,
                                  const int* __restrict__ cols,
                                  int nnz) {
    int idx = blockIdx.x * blockDim.x + threadIdx.x;
    int g = idx >> 4;
    int t = idx & 15;
    if (g >= nnz) return;
    int row = rows[g];
    int col = cols[g];
    float v = vals[g];
    float4 xv = reinterpret_cast<const float4*>(x)[row * F4 + t];
    red_add_v4(&g_he[(size_t)col * FDIM + t * 4],
               xv.x * v, xv.y * v, xv.z * v, xv.w * v);
}

// Phase B: out[row][r][:] += val * rank_masks[r][he_idxs[col]] * he_feat[col][:]
// for r = 0..2 only (rank 3 is overwritten with x by the reference).
__global__ void scatter_out_kernel(const float* __restrict__ rank_masks,
                                   const float* __restrict__ vals,
                                   const int* __restrict__ he_idxs,
                                   const int* __restrict__ rows,
                                   const int* __restrict__ cols,
                                   float* __restrict__ out,
                                   int nnz, int E) {
    int idx = blockIdx.x * blockDim.x + threadIdx.x;
    int g = idx >> 4;
    int t = idx & 15;
    if (g >= nnz) return;
    int row = rows[g];
    int col = cols[g];
    float v = vals[g];
    int he = he_idxs[col];
    float m0 = rank_masks[he] * v;
    float m1 = rank_masks[E + he] * v;
    float m2 = rank_masks[2 * E + he] * v;
    float4 h = reinterpret_cast<const float4*>(g_he)[(size_t)col * F4 + t];
    float* base = out + (size_t)row * (RDIM * FDIM) + t * 4;
    red_add_v4(base + 0 * FDIM, h.x * m0, h.y * m0, h.z * m0, h.w * m0);
    red_add_v4(base + 1 * FDIM, h.x * m1, h.y * m1, h.z * m1, h.w * m1);
    red_add_v4(base + 2 * FDIM, h.x * m2, h.y * m2, h.z * m2, h.w * m2);
}

extern "C" void kernel_launch(void* const* d_in, const int* in_sizes, int n_in,
                              void* d_out, int out_size) {
    const float* x          = (const float*)d_in[0];   // (N, F)
    const float* rank_masks = (const float*)d_in[1];   // (R, E)
    const float* vals       = (const float*)d_in[2];   // (NNZ,)
    const int*   he_idxs    = (const int*)d_in[3];     // (E,)   int32 (jax x64 off)
    const int*   rows       = (const int*)d_in[4];     // (NNZ,) int32
    const int*   cols       = (const int*)d_in[5];     // (NNZ,) int32
    float* out = (float*)d_out;

    int nnz = in_sizes[2];
    int E   = in_sizes[3];
    int N   = in_sizes[0] / FDIM;

    {
        int total = N * (RDIM * F4) + E * F4;
        int threads = 256;
        int blocks = (total + threads - 1) / threads;
        init_kernel<<<blocks, threads>>>(x, out, N, E);
    }
    {
        long long total = (long long)nnz * 16;
        int threads = 256;
        int blocks = (int)((total + threads - 1) / threads);
        scatter_he_kernel<<<blocks, threads>>>(x, vals, rows, cols, nnz);
    }
    {
        long long total = (long long)nnz * 16;
        int threads = 256;
        int blocks = (int)((total + threads - 1) / threads);
        scatter_out_kernel<<<blocks, threads>>>(rank_masks, vals, he_idxs, rows, cols,
                                                out, nnz, E);
    }
}

// round 4
// speedup vs baseline: 1.4211x; 1.4211x over previous
#include <cuda_runtime.h>

#define FDIM 64
#define RDIM 4
#define F4   16
#define N_MAX   100000
#define E_MAX   100000
#define NNZ_MAX 800000
#define SCAN_B  1024

// Device-global scratch (no allocations allowed).
__device__ float g_he[(size_t)E_MAX * FDIM];              // 25.6 MB
__device__ int   g_cnt[N_MAX + E_MAX];                    // degree counts (rows ++ cols)
__device__ int   g_fill[N_MAX + E_MAX];                   // placement cursors
__device__ int   g_ptr[N_MAX + E_MAX + 1];                // exclusive scan of g_cnt
__device__ int   g_bsum[(N_MAX + E_MAX) / SCAN_B + 2];    // per-block scan sums
__device__ int   g_idx[2 * NNZ_MAX];                      // CSR ids then CSC ids

// ---- build step ---------------------------------------------------------

__global__ void zero_kernel(int total) {
    int i = blockIdx.x * blockDim.x + threadIdx.x;
    if (i < total) { g_cnt[i] = 0; g_fill[i] = 0; }
}

__global__ void hist_kernel(const int* __restrict__ rows,
                            const int* __restrict__ cols, int nnz, int N) {
    int i = blockIdx.x * blockDim.x + threadIdx.x;
    if (i >= nnz) return;
    atomicAdd(&g_cnt[rows[i]], 1);
    atomicAdd(&g_cnt[N + cols[i]], 1);
}

__global__ void scan1_kernel(int n) {
    __shared__ int sh[SCAN_B];
    int i = blockIdx.x * SCAN_B + threadIdx.x;
    int v = (i < n) ? g_cnt[i] : 0;
    sh[threadIdx.x] = v;
    __syncthreads();
    for (int off = 1; off < SCAN_B; off <<= 1) {
        int t = (threadIdx.x >= off) ? sh[threadIdx.x - off] : 0;
        __syncthreads();
        sh[threadIdx.x] += t;
        __syncthreads();
    }
    if (i < n) g_ptr[i] = sh[threadIdx.x] - v;            // exclusive within block
    if (threadIdx.x == SCAN_B - 1) g_bsum[blockIdx.x] = sh[threadIdx.x];
}

__global__ void scan2_kernel(int nb) {                    // single block
    __shared__ int sh[SCAN_B];
    int v = (threadIdx.x < nb) ? g_bsum[threadIdx.x] : 0;
    sh[threadIdx.x] = v;
    __syncthreads();
    for (int off = 1; off < SCAN_B; off <<= 1) {
        int t = (threadIdx.x >= off) ? sh[threadIdx.x - off] : 0;
        __syncthreads();
        sh[threadIdx.x] += t;
        __syncthreads();
    }
    if (threadIdx.x < nb) g_bsum[threadIdx.x] = sh[threadIdx.x] - v;  // exclusive
}

__global__ void scan3_kernel(int n, int nnz2) {
    int i = blockIdx.x * blockDim.x + threadIdx.x;
    if (i < n) g_ptr[i] += g_bsum[i / SCAN_B];
    if (i == 0) g_ptr[n] = nnz2;                           // total sentinel
}

__global__ void place_kernel(const int* __restrict__ rows,
                             const int* __restrict__ cols, int nnz, int N) {
    int i = blockIdx.x * blockDim.x + threadIdx.x;
    if (i >= nnz) return;
    int r = rows[i];
    int c = N + cols[i];
    int p1 = g_ptr[r] + atomicAdd(&g_fill[r], 1);
    g_idx[p1] = i;
    int p2 = g_ptr[c] + atomicAdd(&g_fill[c], 1);
    g_idx[p2] = i;
}

// ---- phase A: he[e] = sum over incident nnz of v * x[row]  (gather) -----

__global__ void he_gather_kernel(const float* __restrict__ x,
                                 const float* __restrict__ vals,
                                 const int* __restrict__ rows,
                                 int E, int N) {
    int idx = blockIdx.x * blockDim.x + threadIdx.x;
    int e = idx >> 4;
    int t = idx & 15;
    if (e >= E) return;
    int beg = g_ptr[N + e];
    int end = g_ptr[N + e + 1];
    const float4* x4 = reinterpret_cast<const float4*>(x);
    float4 acc = make_float4(0.f, 0.f, 0.f, 0.f);
    for (int k = beg; k < end; k++) {
        int j = g_idx[k];
        float v = vals[j];
        float4 xv = x4[rows[j] * F4 + t];
        acc.x += v * xv.x; acc.y += v * xv.y;
        acc.z += v * xv.z; acc.w += v * xv.w;
    }
    reinterpret_cast<float4*>(g_he)[(size_t)e * F4 + t] = acc;
}

// ---- phase B: out[n][r] = sum v*m_r*he[col] (ranks 0-2), out[n][3] = x[n]

__global__ void out_gather_kernel(const float* __restrict__ x,
                                  const float* __restrict__ rank_masks,
                                  const float* __restrict__ vals,
                                  const int* __restrict__ he_idxs,
                                  const int* __restrict__ cols,
                                  float* __restrict__ out,
                                  int N, int E) {
    int idx = blockIdx.x * blockDim.x + threadIdx.x;
    int n = idx >> 4;
    int t = idx & 15;
    if (n >= N) return;
    int beg = g_ptr[n];
    int end = g_ptr[n + 1];
    const float4* he4 = reinterpret_cast<const float4*>(g_he);
    float4 a0 = make_float4(0.f, 0.f, 0.f, 0.f);
    float4 a1 = a0, a2 = a0;
    for (int k = beg; k < end; k++) {
        int j  = g_idx[k];
        int c  = cols[j];
        float v = vals[j];
        int he = he_idxs[c];
        float m0 = rank_masks[he] * v;
        float m1 = rank_masks[E + he] * v;
        float m2 = rank_masks[2 * E + he] * v;
        float4 h = he4[(size_t)c * F4 + t];
        a0.x += m0 * h.x; a0.y += m0 * h.y; a0.z += m0 * h.z; a0.w += m0 * h.w;
        a1.x += m1 * h.x; a1.y += m1 * h.y; a1.z += m1 * h.z; a1.w += m1 * h.w;
        a2.x += m2 * h.x; a2.y += m2 * h.y; a2.z += m2 * h.z; a2.w += m2 * h.w;
    }
    float4* out4 = reinterpret_cast<float4*>(out);
    size_t base = (size_t)n * (RDIM * F4);
    out4[base + 0 * F4 + t] = a0;
    out4[base + 1 * F4 + t] = a1;
    out4[base + 2 * F4 + t] = a2;
    out4[base + 3 * F4 + t] = reinterpret_cast<const float4*>(x)[n * F4 + t];
}

// ---- launch -------------------------------------------------------------

extern "C" void kernel_launch(void* const* d_in, const int* in_sizes, int n_in,
                              void* d_out, int out_size) {
    const float* x          = (const float*)d_in[0];
    const float* rank_masks = (const float*)d_in[1];
    const float* vals       = (const float*)d_in[2];
    const int*   he_idxs    = (const int*)d_in[3];
    const int*   rows       = (const int*)d_in[4];
    const int*   cols       = (const int*)d_in[5];
    float* out = (float*)d_out;

    int nnz = in_sizes[2];
    int E   = in_sizes[3];
    int N   = in_sizes[0] / FDIM;
    int total = N + E;
    int nb = (total + SCAN_B - 1) / SCAN_B;

    zero_kernel<<<(total + 255) / 256, 256>>>(total);
    hist_kernel<<<(nnz + 255) / 256, 256>>>(rows, cols, nnz, N);
    scan1_kernel<<<nb, SCAN_B>>>(total);
    scan2_kernel<<<1, SCAN_B>>>(nb);
    scan3_kernel<<<(total + 255) / 256, 256>>>(total, 2 * nnz);
    place_kernel<<<(nnz + 255) / 256, 256>>>(rows, cols, nnz, N);

    {
        long long th = (long long)E * 16;
        he_gather_kernel<<<(int)((th + 255) / 256), 256>>>(x, vals, rows, E, N);
    }
    {
        long long th = (long long)N * 16;
        out_gather_kernel<<<(int)((th + 255) / 256), 256>>>(x, rank_masks, vals,
                                                            he_idxs, cols, out, N, E);
    }
}